// round 1
// baseline (speedup 1.0000x reference)
#include <cuda_runtime.h>

// Problem constants (fixed by the reference)
constexpr int NB   = 32;   // neighbors per query
constexpr int A    = 4;    // anchors
constexpr int K    = 15;   // kernel points
constexpr int KP   = 16;   // padded K
constexpr int CIN  = 32;
constexpr int COUT = 32;
constexpr float INV_EXT = 1.0f / 0.6f;   // 1 / KP_EXTENT

// Tiny precomputed tables: rotated kernel points + their squared norms
__device__ float g_rot_kp[A][K][3];
__device__ float g_k2[A][K];

__global__ void precompute_kernel(const float* __restrict__ kp,
                                  const float* __restrict__ anchors) {
    int idx = threadIdx.x;
    if (idx < A * K) {
        int a = idx / K;
        int k = idx - a * K;
        float p0 = kp[k * 3 + 0], p1 = kp[k * 3 + 1], p2 = kp[k * 3 + 2];
        const float* R = anchors + a * 9;
        float r0 = R[0] * p0 + R[1] * p1 + R[2] * p2;
        float r1 = R[3] * p0 + R[4] * p1 + R[5] * p2;
        float r2 = R[6] * p0 + R[7] * p1 + R[8] * p2;
        g_rot_kp[a][k][0] = r0;
        g_rot_kp[a][k][1] = r1;
        g_rot_kp[a][k][2] = r2;
        g_k2[a][k] = r0 * r0 + r1 * r1 + r2 * r2;
    }
}

// One block per query point. 4 warps, warp w handles anchor a = w.
__global__ __launch_bounds__(128, 8) void kpconv_kernel(
    const float* __restrict__ q_pts,    // [N,3]
    const float* __restrict__ s_pts,    // [M,3]
    const int*   __restrict__ nbr,      // [N,NB]
    const float* __restrict__ x,        // [M,A,CIN]
    const float* __restrict__ weights,  // [K,CIN,COUT]
    float*       __restrict__ out)      // [N,A,COUT]
{
    const int n    = blockIdx.x;
    const int tid  = threadIdx.x;
    const int a    = tid >> 5;
    const int lane = tid & 31;

    __shared__ float s_diff[NB][3];
    __shared__ float s_n2[NB];
    __shared__ int   s_ind[NB];
    __shared__ float s_w[A][NB][KP];       // KP influence weights, padded
    __shared__ float s_wf[A][K][CIN];      // weighted features

    // ---- neighbor gather + centering (warp 0 lanes, 1 neighbor each) ----
    if (tid < NB) {
        int m = nbr[n * NB + tid];
        s_ind[tid] = m;
        float dx = s_pts[m * 3 + 0] - q_pts[n * 3 + 0];
        float dy = s_pts[m * 3 + 1] - q_pts[n * 3 + 1];
        float dz = s_pts[m * 3 + 2] - q_pts[n * 3 + 2];
        s_diff[tid][0] = dx;
        s_diff[tid][1] = dy;
        s_diff[tid][2] = dz;
        s_n2[tid] = dx * dx + dy * dy + dz * dz;
    }
    __syncthreads();

    // ---- KP influence weights: lane = neighbor b, loop over k ----
    {
        float dx = s_diff[lane][0];
        float dy = s_diff[lane][1];
        float dz = s_diff[lane][2];
        float n2 = s_n2[lane];
        #pragma unroll
        for (int k = 0; k < K; k++) {
            float r0 = g_rot_kp[a][k][0];
            float r1 = g_rot_kp[a][k][1];
            float r2 = g_rot_kp[a][k][2];
            float cross = dx * r0 + dy * r1 + dz * r2;
            float sq = n2 + g_k2[a][k] - 2.0f * cross;
            sq = fmaxf(sq, 1e-12f);
            float w = fmaxf(1.0f - sqrtf(sq) * INV_EXT, 0.0f);
            s_w[a][lane][k] = w;
        }
        s_w[a][lane][K] = 0.0f;  // pad
    }
    __syncwarp();

    // ---- Stage 1: weighted feature accumulation. lane = input channel c ----
    float wf[K];
    #pragma unroll
    for (int k = 0; k < K; k++) wf[k] = 0.0f;

    #pragma unroll 4
    for (int b = 0; b < NB; b++) {
        // coalesced 128B gather per warp; streaming hint keeps L1 for weights
        float xv = __ldcs(&x[((long)s_ind[b] * A + a) * CIN + lane]);
        const float4* wp = reinterpret_cast<const float4*>(&s_w[a][b][0]);
        float4 w0 = wp[0], w1 = wp[1], w2 = wp[2], w3 = wp[3];
        wf[0]  = fmaf(w0.x, xv, wf[0]);
        wf[1]  = fmaf(w0.y, xv, wf[1]);
        wf[2]  = fmaf(w0.z, xv, wf[2]);
        wf[3]  = fmaf(w0.w, xv, wf[3]);
        wf[4]  = fmaf(w1.x, xv, wf[4]);
        wf[5]  = fmaf(w1.y, xv, wf[5]);
        wf[6]  = fmaf(w1.z, xv, wf[6]);
        wf[7]  = fmaf(w1.w, xv, wf[7]);
        wf[8]  = fmaf(w2.x, xv, wf[8]);
        wf[9]  = fmaf(w2.y, xv, wf[9]);
        wf[10] = fmaf(w2.z, xv, wf[10]);
        wf[11] = fmaf(w2.w, xv, wf[11]);
        wf[12] = fmaf(w3.x, xv, wf[12]);
        wf[13] = fmaf(w3.y, xv, wf[13]);
        wf[14] = fmaf(w3.z, xv, wf[14]);
    }

    #pragma unroll
    for (int k = 0; k < K; k++) s_wf[a][k][lane] = wf[k];
    __syncwarp();

    // ---- Stage 2: [K*CIN] x [K*CIN, COUT] GEMV. lane = output channel d ----
    float acc = 0.0f;
    for (int k = 0; k < K; k++) {
        const float* wrow = weights + k * CIN * COUT + lane;
        #pragma unroll
        for (int c = 0; c < CIN; c++) {
            acc = fmaf(s_wf[a][k][c], __ldg(&wrow[c * COUT]), acc);
        }
    }
    out[(n * A + a) * COUT + lane] = acc;
}

extern "C" void kernel_launch(void* const* d_in, const int* in_sizes, int n_in,
                              void* d_out, int out_size) {
    const float* q_pts   = (const float*)d_in[0];
    const float* s_pts   = (const float*)d_in[1];
    const int*   nbr     = (const int*)  d_in[2];
    const float* x       = (const float*)d_in[3];
    const float* kp      = (const float*)d_in[4];
    const float* anchors = (const float*)d_in[5];
    const float* weights = (const float*)d_in[6];
    float* out = (float*)d_out;

    const int Nq = in_sizes[2] / NB;   // 16000

    precompute_kernel<<<1, 64>>>(kp, anchors);
    kpconv_kernel<<<Nq, 128>>>(q_pts, s_pts, nbr, x, weights, out);
}